// round 1
// baseline (speedup 1.0000x reference)
#include <cuda_runtime.h>
#include <stdint.h>

#define BB   8
#define NN   4096
#define CPN  57
#define KK   16
#define THR  0.04f

// ---------------- scratch (device globals; no allocation allowed) -----------
__device__ int   g_knn_idx[BB * NN * KK];
__device__ float g_knn_dist[BB * NN * KK];

// ============================================================================
// Kernel A: ball-kNN.  One thread per query point; candidate tiles in SMEM.
// Distance formula matches the reference: (sq_i + sq_j) - 2*dot, no fusion of
// the final sub so rounding follows the reference's mul-then-sub structure.
// Only candidates with d <= r^2 can ever be kept (out-of-ball -> self anyway),
// so the divergent top-16 insert runs on ~3% of candidates.
// ============================================================================
__global__ void knn_kernel(const float* __restrict__ xyz) {
    __shared__ float4 tile[1024];
    const int b = blockIdx.y;
    const int i = blockIdx.x * 128 + threadIdx.x;
    const float* bx = xyz + (size_t)b * NN * 3;

    const float qx = bx[i * 3 + 0];
    const float qy = bx[i * 3 + 1];
    const float qz = bx[i * 3 + 2];
    const float qsq = fmaf(qz, qz, fmaf(qy, qy, qx * qx));

    float bestd[KK];
    int   bestj[KK];
#pragma unroll
    for (int s = 0; s < KK; s++) { bestd[s] = 3.0e38f; bestj[s] = i; }
    float maxv = 3.0e38f;
    int   maxslot = 0;
    int   maxj = i;

    for (int t = 0; t < NN; t += 1024) {
        for (int s = threadIdx.x; s < 1024; s += 128) {
            float x = bx[(t + s) * 3 + 0];
            float y = bx[(t + s) * 3 + 1];
            float z = bx[(t + s) * 3 + 2];
            tile[s] = make_float4(x, y, z, fmaf(z, z, fmaf(y, y, x * x)));
        }
        __syncthreads();

#pragma unroll 4
        for (int s = 0; s < 1024; s++) {
            float4 c = tile[s];
            float dot = fmaf(qz, c.z, fmaf(qy, c.y, qx * c.x));
            float t1  = qsq + c.w;
            float d   = __fsub_rn(t1, __fmul_rn(2.0f, dot));
            int   j   = t + s;
            if (d <= THR && d < maxv) {
                // replace current max slot (predicated, no register spills)
#pragma unroll
                for (int u = 0; u < KK; u++)
                    if (u == maxslot) { bestd[u] = d; bestj[u] = j; }
                // rescan for new max; on value ties evict the HIGHER index
                // (matches top_k's lower-index preference)
                maxv = bestd[0]; maxj = bestj[0]; maxslot = 0;
#pragma unroll
                for (int u = 1; u < KK; u++) {
                    bool g = (bestd[u] > maxv) ||
                             (bestd[u] == maxv && bestj[u] > maxj);
                    if (g) { maxv = bestd[u]; maxj = bestj[u]; maxslot = u; }
                }
            }
        }
        __syncthreads();
    }

    const int base = (b * NN + i) * KK;
#pragma unroll
    for (int s = 0; s < KK; s++) {
        float d = fmaxf(bestd[s], 0.0f);
        int   j = bestj[s];
        if (d > THR) { j = i; d = 0.0f; }   // pad / mask with self
        g_knn_idx[base + s]  = j;
        g_knn_dist[base + s] = d;
    }
}

// ============================================================================
// Kernel B: full feature pipeline.  One warp per point, 16 warps/block,
// 4 points per warp (64 points/block).  All weights staged in SMEM once per
// block.  Channel layout: lane owns channels (2*lane, 2*lane+1) -> weight rows
// read as conflict-free LDS.64; hidden vectors broadcast from per-warp SMEM.
// ============================================================================
#define WARPS 16
#define PPW   4
#define TPB   (WARPS * 32)

// float offsets into dynamic shared memory
#define O_W1   0                 // [7][64]
#define O_B1   448
#define O_W2   512               // [64][64]
#define O_B2   4608
#define O_M1   4672              // [67][128]
#define O_MB1  13248
#define O_M2   13376             // [128][64]
#define O_MB2  21568
#define O_SC   21632             // [57][64]
#define O_SCB  25280
#define O_HID  25344             // per-warp 64
#define O_H128 26368             // per-warp 128
#define SMEM_FLOATS 28416
#define SMEM_BYTES  (SMEM_FLOATS * 4)

__global__ __launch_bounds__(TPB, 1)
void feat_kernel(const float* __restrict__ xyz,
                 const float* __restrict__ points,
                 const float* __restrict__ w1, const float* __restrict__ b1,
                 const float* __restrict__ w2, const float* __restrict__ b2,
                 const float* __restrict__ m1, const float* __restrict__ mb1,
                 const float* __restrict__ m2, const float* __restrict__ mb2,
                 const float* __restrict__ sc, const float* __restrict__ scb,
                 float* __restrict__ out) {
    extern __shared__ float sm[];

    // ---- cooperative weight staging -------------------------------------
    for (int t = threadIdx.x; t < 448; t += TPB)  sm[O_W1 + t]  = w1[t];
    for (int t = threadIdx.x; t < 64;  t += TPB)  sm[O_B1 + t]  = b1[t];
    for (int t = threadIdx.x; t < 4096; t += TPB) sm[O_W2 + t]  = w2[t];
    for (int t = threadIdx.x; t < 64;  t += TPB)  sm[O_B2 + t]  = b2[t];
    for (int t = threadIdx.x; t < 8576; t += TPB) sm[O_M1 + t]  = m1[t];
    for (int t = threadIdx.x; t < 128; t += TPB)  sm[O_MB1 + t] = mb1[t];
    for (int t = threadIdx.x; t < 8192; t += TPB) sm[O_M2 + t]  = m2[t];
    for (int t = threadIdx.x; t < 64;  t += TPB)  sm[O_MB2 + t] = mb2[t];
    for (int t = threadIdx.x; t < 3648; t += TPB) sm[O_SC + t]  = sc[t];
    for (int t = threadIdx.x; t < 64;  t += TPB)  sm[O_SCB + t] = scb[t];
    __syncthreads();

    const int warp = threadIdx.x >> 5;
    const int lane = threadIdx.x & 31;
    const int c0 = 2 * lane, c1 = c0 + 1;
    const int c4 = 4 * lane;

    // W1 columns + biases for this lane's channels, reused across all points
    float w1r0[7], w1r1[7];
#pragma unroll
    for (int t = 0; t < 7; t++) {
        w1r0[t] = sm[O_W1 + t * 64 + c0];
        w1r1[t] = sm[O_W1 + t * 64 + c1];
    }
    const float lb10 = sm[O_B1 + c0], lb11 = sm[O_B1 + c1];
    const float lb20 = sm[O_B2 + c0], lb21 = sm[O_B2 + c1];

    float* hid  = sm + O_HID  + warp * 64;
    float* h128 = sm + O_H128 + warp * 128;

    for (int pp = 0; pp < PPW; pp++) {
        const int p = blockIdx.x * (WARPS * PPW) + warp * PPW + pp;
        const int b = p >> 12;
        const float* q = xyz + (size_t)p * 3;
        const float qx = q[0], qy = q[1], qz = q[2];

        int   myidx = p;
        float mydist = 0.0f;
        if (lane < KK) {
            myidx  = g_knn_idx[p * KK + lane];
            mydist = g_knn_dist[p * KK + lane];
        }

        float agg0 = 0.0f, agg1 = 0.0f;

        for (int k = 0; k < KK; k++) {
            const int   j  = __shfl_sync(0xffffffffu, myidx, k);
            const float dk = __shfl_sync(0xffffffffu, mydist, k);
            const float* nb = xyz + ((size_t)(b << 12) + j) * 3;
            const float g0 = nb[0], g1 = nb[1], g2 = nb[2];
            const float g3 = g0 - qx, g4 = g1 - qy, g5 = g2 - qz;

            // dfg layer 1: [7] -> [64], ReLU
            float h0 = lb10, h1 = lb11;
            h0 = fmaf(g0, w1r0[0], h0); h1 = fmaf(g0, w1r1[0], h1);
            h0 = fmaf(g1, w1r0[1], h0); h1 = fmaf(g1, w1r1[1], h1);
            h0 = fmaf(g2, w1r0[2], h0); h1 = fmaf(g2, w1r1[2], h1);
            h0 = fmaf(g3, w1r0[3], h0); h1 = fmaf(g3, w1r1[3], h1);
            h0 = fmaf(g4, w1r0[4], h0); h1 = fmaf(g4, w1r1[4], h1);
            h0 = fmaf(g5, w1r0[5], h0); h1 = fmaf(g5, w1r1[5], h1);
            h0 = fmaf(dk, w1r0[6], h0); h1 = fmaf(dk, w1r1[6], h1);
            h0 = fmaxf(h0, 0.0f); h1 = fmaxf(h1, 0.0f);
            *(float2*)&hid[c0] = make_float2(h0, h1);
            __syncwarp();

            // dfg layer 2: [64] -> [64] (no ReLU)
            float o0 = lb20, o1 = lb21;
#pragma unroll
            for (int t = 0; t < 64; t++) {
                const float hv = hid[t];
                const float2 w = *(const float2*)&sm[O_W2 + t * 64 + c0];
                o0 = fmaf(hv, w.x, o0);
                o1 = fmaf(hv, w.y, o1);
            }

            // grouped_points: [g7(7) | points(57)]
            const float* prow = points + ((size_t)(b << 12) + j) * CPN;
            float gp0 = (c0 >= 7) ? prow[c0 - 7] : 0.0f;
            float gp1 = (c1 >= 7) ? prow[c1 - 7] : 0.0f;
            if (lane == 0)      { gp0 = g0; gp1 = g1; }
            else if (lane == 1) { gp0 = g2; gp1 = g3; }
            else if (lane == 2) { gp0 = g4; gp1 = g5; }
            else if (lane == 3) { gp0 = dk; }

            agg0 = fmaf(o0, gp0, agg0);
            agg1 = fmaf(o1, gp1, agg1);
            __syncwarp();
        }
        agg0 *= 0.0625f; agg1 *= 0.0625f;

        // h67 = [xyz, agg]; agg broadcast via hid buffer
        *(float2*)&hid[c0] = make_float2(agg0, agg1);
        __syncwarp();

        // mlp1: [67] -> [128], ReLU.  Lane owns 4 channels (c4..c4+3).
        const float qv[3] = {qx, qy, qz};
        float4 acc = *(const float4*)&sm[O_MB1 + c4];
#pragma unroll
        for (int t = 0; t < 67; t++) {
            const float v = (t < 3) ? qv[t] : hid[t - 3];
            const float4 w = *(const float4*)&sm[O_M1 + t * 128 + c4];
            acc.x = fmaf(v, w.x, acc.x);
            acc.y = fmaf(v, w.y, acc.y);
            acc.z = fmaf(v, w.z, acc.z);
            acc.w = fmaf(v, w.w, acc.w);
        }
        acc.x = fmaxf(acc.x, 0.0f); acc.y = fmaxf(acc.y, 0.0f);
        acc.z = fmaxf(acc.z, 0.0f); acc.w = fmaxf(acc.w, 0.0f);
        *(float4*)&h128[c4] = acc;
        __syncwarp();

        // stage self points row (for shortcut) into hid buffer
        const float* pself = points + (size_t)p * CPN;
        for (int t = lane; t < CPN; t += 32) hid[t] = pself[t];
        __syncwarp();

        // mlp2: [128] -> [64] (no ReLU before add)
        float o0 = sm[O_MB2 + c0], o1 = sm[O_MB2 + c1];
#pragma unroll 16
        for (int t = 0; t < 128; t++) {
            const float hv = h128[t];
            const float2 w = *(const float2*)&sm[O_M2 + t * 64 + c0];
            o0 = fmaf(hv, w.x, o0);
            o1 = fmaf(hv, w.y, o1);
        }

        // shortcut: points @ sc_w + sc_b
        float r0 = sm[O_SCB + c0], r1 = sm[O_SCB + c1];
#pragma unroll
        for (int t = 0; t < CPN; t++) {
            const float pv = hid[t];
            const float2 w = *(const float2*)&sm[O_SC + t * 64 + c0];
            r0 = fmaf(pv, w.x, r0);
            r1 = fmaf(pv, w.y, r1);
        }

        float2 res = make_float2(fmaxf(r0 + o0, 0.0f), fmaxf(r1 + o1, 0.0f));
        *(float2*)&out[(size_t)p * 64 + c0] = res;
        __syncwarp();
    }
}

// ============================================================================
extern "C" void kernel_launch(void* const* d_in, const int* in_sizes, int n_in,
                              void* d_out, int out_size) {
    const float* xyz    = (const float*)d_in[0];
    const float* points = (const float*)d_in[1];
    const float* w1     = (const float*)d_in[2];
    const float* b1     = (const float*)d_in[3];
    const float* w2     = (const float*)d_in[4];
    const float* b2     = (const float*)d_in[5];
    const float* m1     = (const float*)d_in[6];
    const float* mb1    = (const float*)d_in[7];
    const float* m2     = (const float*)d_in[8];
    const float* mb2    = (const float*)d_in[9];
    const float* sc     = (const float*)d_in[10];
    const float* scb    = (const float*)d_in[11];
    float* out = (float*)d_out;

    (void)in_sizes; (void)n_in; (void)out_size;

    dim3 gA(NN / 128, BB);
    knn_kernel<<<gA, 128>>>(xyz);

    cudaFuncSetAttribute(feat_kernel,
                         cudaFuncAttributeMaxDynamicSharedMemorySize,
                         SMEM_BYTES);
    feat_kernel<<<BB * NN / (WARPS * PPW), TPB, SMEM_BYTES>>>(
        xyz, points, w1, b1, w2, b2, m1, mb1, m2, mb2, sc, scb, out);
}

// round 2
// speedup vs baseline: 1.9069x; 1.9069x over previous
#include <cuda_runtime.h>
#include <stdint.h>

#define BB   8
#define NN   4096
#define CPN  57
#define KK   16
#define THR  0.04f
#define GC   5
#define NC   125

// ---------------- scratch (device globals; no allocation allowed) -----------
__device__ int    g_knn_idx[BB * NN * KK];
__device__ float  g_knn_dist[BB * NN * KK];
__device__ int    g_cnt[BB * 128];
__device__ int    g_off[BB * 128];
__device__ int    g_cur[BB * 128];
__device__ float4 g_sx[BB * NN];
__device__ int    g_sj[BB * NN];

// ---------------------------------------------------------------------------
// f32x2 packed helpers
// ---------------------------------------------------------------------------
typedef unsigned long long u64;
__device__ __forceinline__ u64 f2pack(float a, float b) {
    u64 r; asm("mov.b64 %0,{%1,%2};" : "=l"(r) : "f"(a), "f"(b)); return r;
}
__device__ __forceinline__ void f2unpack(u64 v, float& a, float& b) {
    asm("mov.b64 {%0,%1},%2;" : "=f"(a), "=f"(b) : "l"(v));
}
__device__ __forceinline__ u64 ffma2(u64 a, u64 b, u64 c) {
    u64 d; asm("fma.rn.f32x2 %0,%1,%2,%3;" : "=l"(d) : "l"(a), "l"(b), "l"(c));
    return d;
}
__device__ __forceinline__ void lds2x64(u64& a, u64& b, unsigned addr) {
    asm volatile("ld.shared.v2.b64 {%0,%1},[%2];"
                 : "=l"(a), "=l"(b) : "r"(addr));
}

// ---------------------------------------------------------------------------
// Grid build: cell id (cell size == radius == 0.2, 5^3 cells per batch)
// ---------------------------------------------------------------------------
__device__ __forceinline__ int cell_of(float x, float y, float z) {
    int cx = min((int)(x * 5.0f), 4);
    int cy = min((int)(y * 5.0f), 4);
    int cz = min((int)(z * 5.0f), 4);
    return (cx * 5 + cy) * 5 + cz;
}

__global__ void grid_zero() {
    int t = blockIdx.x * 256 + threadIdx.x;
    if (t < BB * 128) g_cnt[t] = 0;
}

__global__ void grid_count(const float* __restrict__ xyz) {
    int p = blockIdx.x * 256 + threadIdx.x;
    float x = xyz[p * 3 + 0], y = xyz[p * 3 + 1], z = xyz[p * 3 + 2];
    atomicAdd(&g_cnt[(p >> 12) * 128 + cell_of(x, y, z)], 1);
}

__global__ void grid_scan() {
    int b = threadIdx.x;
    if (b < BB) {
        int acc = 0;
        for (int c = 0; c < NC; c++) {
            g_off[b * 128 + c] = acc;
            g_cur[b * 128 + c] = acc;
            acc += g_cnt[b * 128 + c];
        }
        g_off[b * 128 + NC] = acc;   // sentinel
    }
}

__global__ void grid_scatter(const float* __restrict__ xyz) {
    int p = blockIdx.x * 256 + threadIdx.x;
    int b = p >> 12, i = p & (NN - 1);
    float x = xyz[p * 3 + 0], y = xyz[p * 3 + 1], z = xyz[p * 3 + 2];
    int cell = cell_of(x, y, z);
    int pos = atomicAdd(&g_cur[b * 128 + cell], 1);
    float sq = fmaf(z, z, fmaf(y, y, x * x));
    g_sx[(b << 12) + pos] = make_float4(x, y, z, sq);
    g_sj[(b << 12) + pos] = i;
}

// ---------------------------------------------------------------------------
// kNN query: one thread per SORTED point (warp lanes share cell ranges).
// 27-cell scan; cz dim contiguous so (dx,dy) gives one contiguous range.
// Screen: in-ball requires dot >= 0.5*(qsq + csq - r^2); margin covers
// rounding, survivors get the exact reference-rounded distance.
// ---------------------------------------------------------------------------
__global__ void knn_query() {
    const int b = blockIdx.y;
    const int slot = blockIdx.x * 128 + threadIdx.x;
    const float4 q = g_sx[(b << 12) + slot];
    const int qi = g_sj[(b << 12) + slot];
    const float qsq = q.w;
    const int cx = min((int)(q.x * 5.0f), 4);
    const int cy = min((int)(q.y * 5.0f), 4);
    const int cz = min((int)(q.z * 5.0f), 4);
    const float qoff = 0.5f * (qsq - THR) - 1e-5f;

    float bestd[KK];
    int   bestj[KK];
#pragma unroll
    for (int s = 0; s < KK; s++) { bestd[s] = 3.0e38f; bestj[s] = qi; }
    float maxv = 3.0e38f;
    int   maxslot = 0;
    int   maxj = qi;

    const int czlo = max(cz - 1, 0), czhi = min(cz + 1, 4);
    for (int dx = -1; dx <= 1; dx++) {
        int ncx = cx + dx; if (ncx < 0 || ncx > 4) continue;
        for (int dy = -1; dy <= 1; dy++) {
            int ncy = cy + dy; if (ncy < 0 || ncy > 4) continue;
            int cbase = b * 128 + (ncx * 5 + ncy) * 5;
            int sbeg = g_off[cbase + czlo];
            int send = g_off[cbase + czhi + 1];
            for (int s = sbeg; s < send; s++) {
                float4 c = g_sx[(b << 12) + s];
                float dot = fmaf(q.z, c.z, fmaf(q.y, c.y, q.x * c.x));
                float rhs = fmaf(0.5f, c.w, qoff);
                if (dot >= rhs) {
                    float t1 = qsq + c.w;
                    float d = __fsub_rn(t1, __fmul_rn(2.0f, dot));
                    if (d <= THR && d < maxv) {
                        int j = g_sj[(b << 12) + s];
#pragma unroll
                        for (int u = 0; u < KK; u++)
                            if (u == maxslot) { bestd[u] = d; bestj[u] = j; }
                        maxv = bestd[0]; maxj = bestj[0]; maxslot = 0;
#pragma unroll
                        for (int u = 1; u < KK; u++) {
                            bool g = (bestd[u] > maxv) ||
                                     (bestd[u] == maxv && bestj[u] > maxj);
                            if (g) { maxv = bestd[u]; maxj = bestj[u]; maxslot = u; }
                        }
                    }
                }
            }
        }
    }

    const int base = (b * NN + qi) * KK;
#pragma unroll
    for (int s = 0; s < KK; s++) {
        float d = fmaxf(bestd[s], 0.0f);
        int   j = bestj[s];
        if (d > THR) { j = qi; d = 0.0f; }
        g_knn_idx[base + s]  = j;
        g_knn_dist[base + s] = d;
    }
}

// ============================================================================
// feat kernel: one warp per point group (PPW=4), all weights in SMEM.
// dfg2 is k-batched: 16 hidden vectors staged transposed in a swizzled SMEM
// tile; one W2 pass serves all 16 k via packed fma.rn.f32x2.
// mlp1/mlp2/shortcut batched 4 points per weight row.
// ============================================================================
#define WARPS 16
#define PPW   4
#define TPB   (WARPS * 32)

#define O_W1   0
#define O_B1   448
#define O_W2   512
#define O_B2   4608
#define O_M1   4672
#define O_MB1  13248
#define O_M2   13376
#define O_MB2  21568
#define O_SC   21632
#define O_SCB  25280
#define O_SCR  25344
#define WSCR   1552              // floats per warp scratch
// per-warp scratch: hidT @0 (64 rows x stride 20 = 1280)
//                   h67  @1280 (4 x 68 = 272)
//   overlapping hidT after dfg is done: h128 @0 (4x128), prow @512 (4x60)
#define SMEM_FLOATS (O_SCR + WARPS * WSCR)
#define SMEM_BYTES  (SMEM_FLOATS * 4)

__global__ __launch_bounds__(TPB, 1)
void feat_kernel(const float* __restrict__ xyz,
                 const float* __restrict__ points,
                 const float* __restrict__ w1, const float* __restrict__ b1,
                 const float* __restrict__ w2, const float* __restrict__ b2,
                 const float* __restrict__ m1, const float* __restrict__ mb1,
                 const float* __restrict__ m2, const float* __restrict__ mb2,
                 const float* __restrict__ sc, const float* __restrict__ scb,
                 float* __restrict__ out) {
    extern __shared__ float sm[];

    for (int t = threadIdx.x; t < 448; t += TPB)  sm[O_W1 + t]  = w1[t];
    for (int t = threadIdx.x; t < 64;  t += TPB)  sm[O_B1 + t]  = b1[t];
    for (int t = threadIdx.x; t < 4096; t += TPB) sm[O_W2 + t]  = w2[t];
    for (int t = threadIdx.x; t < 64;  t += TPB)  sm[O_B2 + t]  = b2[t];
    for (int t = threadIdx.x; t < 8576; t += TPB) sm[O_M1 + t]  = m1[t];
    for (int t = threadIdx.x; t < 128; t += TPB)  sm[O_MB1 + t] = mb1[t];
    for (int t = threadIdx.x; t < 8192; t += TPB) sm[O_M2 + t]  = m2[t];
    for (int t = threadIdx.x; t < 64;  t += TPB)  sm[O_MB2 + t] = mb2[t];
    for (int t = threadIdx.x; t < 3648; t += TPB) sm[O_SC + t]  = sc[t];
    for (int t = threadIdx.x; t < 64;  t += TPB)  sm[O_SCB + t] = scb[t];
    __syncthreads();

    const int warp = threadIdx.x >> 5;
    const int lane = threadIdx.x & 31;
    const int c0 = 2 * lane, c1 = c0 + 1;
    const int c4 = 4 * lane;

    float w1r0[7], w1r1[7];
#pragma unroll
    for (int t = 0; t < 7; t++) {
        w1r0[t] = sm[O_W1 + t * 64 + c0];
        w1r1[t] = sm[O_W1 + t * 64 + c1];
    }
    const float lb10 = sm[O_B1 + c0], lb11 = sm[O_B1 + c1];
    const float lb20 = sm[O_B2 + c0], lb21 = sm[O_B2 + c1];

    float* ws    = sm + O_SCR + warp * WSCR;   // hidT / h128 / prow
    float* h67   = ws + 1280;                  // 4 x 68
    float* h128b = ws;                         // 4 x 128 (after dfg)
    float* prowb = ws + 512;                   // 4 x 60  (after dfg)

    const unsigned smbase = (unsigned)__cvta_generic_to_shared(sm);
    const unsigned hidT32 = smbase + (unsigned)(O_SCR + warp * WSCR) * 4u;

    const int pbase = blockIdx.x * (WARPS * PPW) + warp * PPW;

    // ---------------- per-point dfg phase --------------------------------
#pragma unroll 1
    for (int pp = 0; pp < PPW; pp++) {
        const int p = pbase + pp;
        const int b = p >> 12;
        const float qx = xyz[p * 3 + 0];
        const float qy = xyz[p * 3 + 1];
        const float qz = xyz[p * 3 + 2];

        int   myidx = p & (NN - 1);
        float mydist = 0.0f;
        if (lane < KK) {
            myidx  = g_knn_idx[p * KK + lane];
            mydist = g_knn_dist[p * KK + lane];
        }

        // ---- dfg layer 1: 4 k at a time, swizzled transpose store -------
        const int sA = (c0 >> 3) & 3;
#pragma unroll
        for (int kb = 0; kb < 4; kb++) {
            float2 hk[4];
#pragma unroll
            for (int kk = 0; kk < 4; kk++) {
                const int k = kb * 4 + kk;
                const int   j  = __shfl_sync(0xffffffffu, myidx, k);
                const float dk = __shfl_sync(0xffffffffu, mydist, k);
                const float* nb = xyz + ((size_t)(b << 12) + j) * 3;
                const float g0 = nb[0], g1 = nb[1], g2 = nb[2];
                const float g3 = g0 - qx, g4 = g1 - qy, g5 = g2 - qz;
                float h0 = lb10, h1 = lb11;
                h0 = fmaf(g0, w1r0[0], h0); h1 = fmaf(g0, w1r1[0], h1);
                h0 = fmaf(g1, w1r0[1], h0); h1 = fmaf(g1, w1r1[1], h1);
                h0 = fmaf(g2, w1r0[2], h0); h1 = fmaf(g2, w1r1[2], h1);
                h0 = fmaf(g3, w1r0[3], h0); h1 = fmaf(g3, w1r1[3], h1);
                h0 = fmaf(g4, w1r0[4], h0); h1 = fmaf(g4, w1r1[4], h1);
                h0 = fmaf(g5, w1r0[5], h0); h1 = fmaf(g5, w1r1[5], h1);
                h0 = fmaf(dk, w1r0[6], h0); h1 = fmaf(dk, w1r1[6], h1);
                hk[kk] = make_float2(fmaxf(h0, 0.0f), fmaxf(h1, 0.0f));
            }
            const int slot = (kb ^ sA) << 2;
            *(float4*)(ws + c0 * 20 + slot) =
                make_float4(hk[0].x, hk[1].x, hk[2].x, hk[3].x);
            *(float4*)(ws + c1 * 20 + slot) =
                make_float4(hk[0].y, hk[1].y, hk[2].y, hk[3].y);
        }
        __syncwarp();

        // ---- dfg layer 2: 16-k batched, f32x2 packed --------------------
        u64 a0[8], a1[8];
        {
            u64 bb0 = f2pack(lb20, lb20), bb1 = f2pack(lb21, lb21);
#pragma unroll
            for (int m = 0; m < 8; m++) { a0[m] = bb0; a1[m] = bb1; }
        }
#pragma unroll
        for (int o = 0; o < 8; o++) {
            const int s = o & 3;
#pragma unroll 4
            for (int tt = 0; tt < 8; tt++) {
                const int t = o * 8 + tt;
                const float2 w = *(const float2*)&sm[O_W2 + t * 64 + c0];
                const u64 w00 = f2pack(w.x, w.x);
                const u64 w11 = f2pack(w.y, w.y);
                const unsigned rowa = hidT32 + (unsigned)(t * 20) * 4u;
                {
                    u64 h01, h23; lds2x64(h01, h23, rowa + 0 * 16);
                    const int m = (0 ^ s) << 1;
                    a0[m] = ffma2(h01, w00, a0[m]); a0[m + 1] = ffma2(h23, w00, a0[m + 1]);
                    a1[m] = ffma2(h01, w11, a1[m]); a1[m + 1] = ffma2(h23, w11, a1[m + 1]);
                }
                {
                    u64 h01, h23; lds2x64(h01, h23, rowa + 1 * 16);
                    const int m = (1 ^ s) << 1;
                    a0[m] = ffma2(h01, w00, a0[m]); a0[m + 1] = ffma2(h23, w00, a0[m + 1]);
                    a1[m] = ffma2(h01, w11, a1[m]); a1[m + 1] = ffma2(h23, w11, a1[m + 1]);
                }
                {
                    u64 h01, h23; lds2x64(h01, h23, rowa + 2 * 16);
                    const int m = (2 ^ s) << 1;
                    a0[m] = ffma2(h01, w00, a0[m]); a0[m + 1] = ffma2(h23, w00, a0[m + 1]);
                    a1[m] = ffma2(h01, w11, a1[m]); a1[m + 1] = ffma2(h23, w11, a1[m + 1]);
                }
                {
                    u64 h01, h23; lds2x64(h01, h23, rowa + 3 * 16);
                    const int m = (3 ^ s) << 1;
                    a0[m] = ffma2(h01, w00, a0[m]); a0[m + 1] = ffma2(h23, w00, a0[m + 1]);
                    a1[m] = ffma2(h01, w11, a1[m]); a1[m + 1] = ffma2(h23, w11, a1[m + 1]);
                }
            }
        }
        __syncwarp();

        // ---- aggregation over k -----------------------------------------
        float agg0 = 0.0f, agg1 = 0.0f;
#pragma unroll
        for (int m = 0; m < 8; m++) {
            float oE0, oO0, oE1, oO1;
            f2unpack(a0[m], oE0, oO0);
            f2unpack(a1[m], oE1, oO1);
#pragma unroll
            for (int kk = 0; kk < 2; kk++) {
                const int k = 2 * m + kk;
                const float o0 = kk ? oO0 : oE0;
                const float o1 = kk ? oO1 : oE1;
                const int   j  = __shfl_sync(0xffffffffu, myidx, k);
                const float dk = __shfl_sync(0xffffffffu, mydist, k);
                const float* nb = xyz + ((size_t)(b << 12) + j) * 3;
                const float g0 = nb[0], g1 = nb[1], g2 = nb[2];
                const float* prow = points + ((size_t)(b << 12) + j) * CPN;
                float gp0 = (c0 >= 7) ? prow[c0 - 7] : 0.0f;
                float gp1 = (c1 >= 7) ? prow[c1 - 7] : 0.0f;
                if (lane == 0)      { gp0 = g0; gp1 = g1; }
                else if (lane == 1) { gp0 = g2; gp1 = g0 - qx; }
                else if (lane == 2) { gp0 = g1 - qy; gp1 = g2 - qz; }
                else if (lane == 3) { gp0 = dk; }
                agg0 = fmaf(o0, gp0, agg0);
                agg1 = fmaf(o1, gp1, agg1);
            }
        }
        agg0 *= 0.0625f; agg1 *= 0.0625f;

        float* hb = h67 + pp * 68;
        if (lane == 0) { hb[0] = qx; hb[1] = qy; hb[2] = qz; }
        hb[3 + c0] = agg0;
        hb[3 + c1] = agg1;
        __syncwarp();
    }

    // ---------------- joint MLP phase (4 points) -------------------------
    // mlp1: [67] -> [128], relu
    {
        u64 acc[PPW][2];
        const float4 bbv = *(const float4*)&sm[O_MB1 + c4];
        const u64 bb01 = f2pack(bbv.x, bbv.y), bb23 = f2pack(bbv.z, bbv.w);
#pragma unroll
        for (int pp = 0; pp < PPW; pp++) { acc[pp][0] = bb01; acc[pp][1] = bb23; }
        const unsigned m1base = smbase + (unsigned)(O_M1 + c4) * 4u;
#pragma unroll 4
        for (int t = 0; t < 67; t++) {
            u64 w01, w23; lds2x64(w01, w23, m1base + (unsigned)(t * 128) * 4u);
#pragma unroll
            for (int pp = 0; pp < PPW; pp++) {
                const float v = h67[pp * 68 + t];
                const u64 vv = f2pack(v, v);
                acc[pp][0] = ffma2(w01, vv, acc[pp][0]);
                acc[pp][1] = ffma2(w23, vv, acc[pp][1]);
            }
        }
        __syncwarp();   // dfg reads of ws fully done before overwrite
#pragma unroll
        for (int pp = 0; pp < PPW; pp++) {
            float x0, x1, x2, x3;
            f2unpack(acc[pp][0], x0, x1);
            f2unpack(acc[pp][1], x2, x3);
            *(float4*)&h128b[pp * 128 + c4] =
                make_float4(fmaxf(x0, 0.0f), fmaxf(x1, 0.0f),
                            fmaxf(x2, 0.0f), fmaxf(x3, 0.0f));
        }
    }

    // stage self point rows
#pragma unroll
    for (int pp = 0; pp < PPW; pp++) {
        const float* ps = points + (size_t)(pbase + pp) * CPN;
        for (int t = lane; t < CPN; t += 32) prowb[pp * 60 + t] = ps[t];
    }
    __syncwarp();

    // mlp2: [128] -> [64]
    u64 om[PPW];
    {
        const u64 mb = *(const u64*)&sm[O_MB2 + c0];
#pragma unroll
        for (int pp = 0; pp < PPW; pp++) om[pp] = mb;
#pragma unroll 4
        for (int t = 0; t < 128; t++) {
            const u64 wp = *(const u64*)&sm[O_M2 + t * 64 + c0];
#pragma unroll
            for (int pp = 0; pp < PPW; pp++) {
                const float v = h128b[pp * 128 + t];
                om[pp] = ffma2(wp, f2pack(v, v), om[pp]);
            }
        }
    }

    // shortcut: points @ sc_w + sc_b
    u64 orr[PPW];
    {
        const u64 sb = *(const u64*)&sm[O_SCB + c0];
#pragma unroll
        for (int pp = 0; pp < PPW; pp++) orr[pp] = sb;
#pragma unroll 4
        for (int t = 0; t < CPN; t++) {
            const u64 wp = *(const u64*)&sm[O_SC + t * 64 + c0];
#pragma unroll
            for (int pp = 0; pp < PPW; pp++) {
                const float v = prowb[pp * 60 + t];
                orr[pp] = ffma2(wp, f2pack(v, v), orr[pp]);
            }
        }
    }

#pragma unroll
    for (int pp = 0; pp < PPW; pp++) {
        float o0, o1, r0, r1;
        f2unpack(om[pp], o0, o1);
        f2unpack(orr[pp], r0, r1);
        const int p = pbase + pp;
        *(float2*)&out[(size_t)p * 64 + c0] =
            make_float2(fmaxf(r0 + o0, 0.0f), fmaxf(r1 + o1, 0.0f));
    }
}

// ============================================================================
extern "C" void kernel_launch(void* const* d_in, const int* in_sizes, int n_in,
                              void* d_out, int out_size) {
    const float* xyz    = (const float*)d_in[0];
    const float* points = (const float*)d_in[1];
    const float* w1     = (const float*)d_in[2];
    const float* b1     = (const float*)d_in[3];
    const float* w2     = (const float*)d_in[4];
    const float* b2     = (const float*)d_in[5];
    const float* m1     = (const float*)d_in[6];
    const float* mb1    = (const float*)d_in[7];
    const float* m2     = (const float*)d_in[8];
    const float* mb2    = (const float*)d_in[9];
    const float* sc     = (const float*)d_in[10];
    const float* scb    = (const float*)d_in[11];
    float* out = (float*)d_out;
    (void)in_sizes; (void)n_in; (void)out_size;

    grid_zero<<<4, 256>>>();
    grid_count<<<BB * NN / 256, 256>>>(xyz);
    grid_scan<<<1, 32>>>();
    grid_scatter<<<BB * NN / 256, 256>>>(xyz);
    knn_query<<<dim3(NN / 128, BB), 128>>>();

    cudaFuncSetAttribute(feat_kernel,
                         cudaFuncAttributeMaxDynamicSharedMemorySize,
                         SMEM_BYTES);
    feat_kernel<<<BB * NN / (WARPS * PPW), TPB, SMEM_BYTES>>>(
        xyz, points, w1, b1, w2, b2, m1, mb1, m2, mb2, sc, scb, out);
}